// round 1
// baseline (speedup 1.0000x reference)
#include <cuda_runtime.h>
#include <cuda_bf16.h>

#define BATCH 8
#define CH    256
#define HH    96
#define WW    96
#define DMAX  4
#define DD    9           // 2*DMAX+1
#define NSH   81          // DD*DD
#define TW    32          // tile width  (threads x)
#define TH    8           // tile height (threads y)
#define CC    8           // channels per smem chunk
#define HALO_H (TH + 2*DMAX)              // 16
#define HALO_W (TW + 2*DMAX)              // 40
#define TILE_ELEMS (CC*HALO_H*HALO_W)     // 5120
#define NLOAD (TILE_ELEMS / 256)          // 20 (exact)
#define STAGE_FLOATS (2*TW*NSH)           // 5184
#define SMEM_FLOATS (STAGE_FLOATS > TILE_ELEMS ? STAGE_FLOATS : TILE_ELEMS)

__global__ __launch_bounds__(256)
void corr_kernel(const float* __restrict__ FM0,
                 const float* __restrict__ FM1,
                 float* __restrict__ out)
{
    __shared__ float smem[SMEM_FLOATS];

    const int tidx = threadIdx.x;        // 0..31 -> w within tile
    const int tidy = threadIdx.y;        // 0..7  -> h within tile
    const int tid  = tidy * TW + tidx;

    const int w0 = blockIdx.x * TW;
    const int h0 = blockIdx.y * TH;
    const int b  = blockIdx.z;

    const int w = w0 + tidx;
    const int h = h0 + tidy;

    float acc[NSH];
#pragma unroll
    for (int i = 0; i < NSH; i++) acc[i] = 0.f;

    const float* fm1b = FM1 + (size_t)b * CH * HH * WW;
    const float* fm0p = FM0 + (size_t)b * CH * HH * WW + (size_t)h * WW + w;

    // Per-thread fixed gather pattern for the halo tile (same every chunk,
    // only the channel base advances). off[j] = offset within (chunk-relative)
    // FM1, or -1 if out of bounds (zero pad).
    int off[NLOAD];
#pragma unroll
    for (int j = 0; j < NLOAD; j++) {
        int idx = tid + 256 * j;                 // < 5120 always
        int cc  = idx / (HALO_H * HALO_W);
        int rem = idx - cc * (HALO_H * HALO_W);
        int r   = rem / HALO_W;
        int col = rem - r * HALO_W;
        int gh = h0 - DMAX + r;
        int gw = w0 - DMAX + col;
        off[j] = ((unsigned)gh < HH && (unsigned)gw < WW)
                   ? (cc * HH + gh) * WW + gw : -1;
    }

    // Prefetch chunk 0 into registers.
    float ld[NLOAD];
#pragma unroll
    for (int j = 0; j < NLOAD; j++) {
        float v = 0.f;
        if (off[j] >= 0) v = fm1b[off[j]];
        ld[j] = v;
    }

#pragma unroll 1
    for (int c0 = 0; c0 < CH; c0 += CC) {
        __syncthreads();               // previous chunk fully consumed
#pragma unroll
        for (int j = 0; j < NLOAD; j++) smem[tid + 256 * j] = ld[j];
        __syncthreads();               // chunk visible to all

        // Prefetch next chunk (LDG latency hidden by the FMA block below).
        if (c0 + CC < CH) {
            const float* nb = fm1b + (size_t)(c0 + CC) * HH * WW;
#pragma unroll
            for (int j = 0; j < NLOAD; j++) {
                float v = 0.f;
                if (off[j] >= 0) v = nb[off[j]];
                ld[j] = v;
            }
        }

        // FM0 scalars for this chunk (coalesced, read exactly once).
        float f0v[CC];
#pragma unroll
        for (int cc = 0; cc < CC; cc++)
            f0v[cc] = fm0p[(size_t)(c0 + cc) * (HH * WW)];

        // 81 shifts x 8 channels of FMAs against the smem halo tile.
#pragma unroll
        for (int cc = 0; cc < CC; cc++) {
            const float f0 = f0v[cc];
            const float* sp = &smem[cc * (HALO_H * HALO_W) + tidy * HALO_W + tidx];
#pragma unroll
            for (int di = 0; di < DD; di++) {
#pragma unroll
                for (int dj = 0; dj < DD; dj++) {
                    acc[di * DD + dj] = fmaf(f0, sp[di * HALO_W + dj],
                                             acc[di * DD + dj]);
                }
            }
        }
    }

    // ---- Coalesced output via smem staging ----
    // out[b,h,w,di,dj]: 81 contiguous floats per pixel (stride 324B). Direct
    // per-thread stores would be ~8x write-amplified; stage 2 rows (64 pixels)
    // at a time and copy linearly.
    __syncthreads();
#pragma unroll 1
    for (int g = 0; g < TH / 2; g++) {
        if ((tidy >> 1) == g) {
            float* sp = &smem[(size_t)((tidy & 1) * TW + tidx) * NSH];
#pragma unroll
            for (int s = 0; s < NSH; s++) sp[s] = acc[s];
        }
        __syncthreads();
#pragma unroll 1
        for (int rr = 0; rr < 2; rr++) {
            const int hrow = h0 + 2 * g + rr;
            float* dst = out + ((size_t)(b * HH + hrow) * WW + w0) * NSH;
            const float* src = &smem[rr * TW * NSH];
            for (int i = tid; i < TW * NSH; i += 256) dst[i] = src[i];
        }
        __syncthreads();
    }
}

extern "C" void kernel_launch(void* const* d_in, const int* in_sizes, int n_in,
                              void* d_out, int out_size)
{
    const float* FM0 = (const float*)d_in[0];
    const float* FM1 = (const float*)d_in[1];
    // d_in[2] = d_max (4), d_in[3] = stride (1): fixed by the problem instance.
    float* out = (float*)d_out;

    dim3 grid(WW / TW, HH / TH, BATCH);   // (3, 12, 8) = 288 blocks
    dim3 block(TW, TH);                   // 256 threads
    corr_kernel<<<grid, block>>>(FM0, FM1, out);
}

// round 2
// speedup vs baseline: 1.9412x; 1.9412x over previous
#include <cuda_runtime.h>
#include <cuda_bf16.h>
#include <cstdint>

#define BATCH 8
#define CH    256
#define HH    96
#define WW    96
#define HW    (HH*WW)
#define DMAX  4
#define DD    9
#define NSH   81
#define TILE_W 32           // pixels per tile in w (2 per thread)
#define TILE_H 16
#define BX 16
#define BY 16
#define NTHR 256
#define CC 4                // channels per pipeline chunk
#define NCHUNK (CH/CC)      // 64
#define HALO_H (TILE_H + 2*DMAX)   // 24
#define HALO_W (TILE_W + 2*DMAX)   // 40
#define HALO_WP 42                  // padded (even: float2 align; halfwarp wavefronts conflict-free)
#define CHUNK_WORDS (CC*HALO_H*HALO_WP)   // 4032
#define LOG_WORDS   (CC*HALO_H*HALO_W)    // 3840
#define NLOAD (LOG_WORDS/NTHR)            // 15

__device__ __forceinline__ void cp_async4(uint32_t dst, const void* src, int sz) {
    asm volatile("cp.async.ca.shared.global [%0], [%1], 4, %2;\n"
                 :: "r"(dst), "l"(src), "r"(sz));
}

__global__ __launch_bounds__(256, 1)
void corr_kernel(const float* __restrict__ FM0,
                 const float* __restrict__ FM1,
                 float* __restrict__ out)
{
    __shared__ float smem[2 * CHUNK_WORDS];   // 32.25 KB, also reused for store staging

    const int tx  = threadIdx.x;        // 0..15
    const int ty  = threadIdx.y;        // 0..15
    const int tid = ty * BX + tx;
    const int w0  = blockIdx.x * TILE_W;
    const int h0  = blockIdx.y * TILE_H;
    const int b   = blockIdx.z;
    const int w   = w0 + 2 * tx;        // even -> float2-aligned everywhere
    const int h   = h0 + ty;

    // ---- per-thread gather tables for the FM1 halo chunk (computed once) ----
    int dstw[NLOAD];
    int srcw[NLOAD];                    // -1 => zero-fill (out of bounds)
#pragma unroll
    for (int j = 0; j < NLOAD; j++) {
        int idx = tid + NTHR * j;       // < 3840
        int cc  = idx / (HALO_H * HALO_W);
        int rem = idx - cc * (HALO_H * HALO_W);
        int r   = rem / HALO_W;
        int col = rem - r * HALO_W;
        dstw[j] = (cc * HALO_H + r) * HALO_WP + col;
        int gh = h0 - DMAX + r;
        int gw = w0 - DMAX + col;
        srcw[j] = ((unsigned)gh < HH && (unsigned)gw < WW)
                    ? cc * HW + gh * WW + gw : -1;
    }

    const float* f1b = FM1 + (size_t)b * CH * HW;
    const uint32_t sbase = (uint32_t)__cvta_generic_to_shared(smem);

    auto issue = [&](int c0, int buf) {
#pragma unroll
        for (int j = 0; j < NLOAD; j++) {
            uint32_t d = sbase + (uint32_t)(buf * CHUNK_WORDS + dstw[j]) * 4u;
            int sw = srcw[j];
            const float* s = f1b + (size_t)c0 * HW + (sw < 0 ? 0 : sw);
            cp_async4(d, s, sw < 0 ? 0 : 4);
        }
        asm volatile("cp.async.commit_group;\n" ::: "memory");
    };

    float acc0[NSH], acc1[NSH];
#pragma unroll
    for (int i = 0; i < NSH; i++) { acc0[i] = 0.f; acc1[i] = 0.f; }

    const float* f0p = FM0 + ((size_t)b * CH) * HW + (size_t)h * WW + w;

    // ---- pipeline prologue ----
    issue(0, 0);
    issue(CC, 1);
    float2 f0cur[CC], f0nxt[CC];
#pragma unroll
    for (int cc = 0; cc < CC; cc++)
        f0cur[cc] = __ldg((const float2*)(f0p + (size_t)cc * HW));

#pragma unroll 1
    for (int ci = 0; ci < NCHUNK; ci++) {
        if (ci < NCHUNK - 1)
            asm volatile("cp.async.wait_group 1;\n" ::: "memory");
        else
            asm volatile("cp.async.wait_group 0;\n" ::: "memory");
        __syncthreads();

        // prefetch FM0 scalars for next chunk
        if (ci + 1 < NCHUNK) {
            const int cn = (ci + 1) * CC;
#pragma unroll
            for (int cc = 0; cc < CC; cc++)
                f0nxt[cc] = __ldg((const float2*)(f0p + (size_t)(cn + cc) * HW));
        }

        const float* sb = &smem[(ci & 1) * CHUNK_WORDS];
#pragma unroll
        for (int cc = 0; cc < CC; cc++) {
            const float f0a = f0cur[cc].x;
            const float f0b = f0cur[cc].y;
            const float* rp = sb + (cc * HALO_H + ty) * HALO_WP + 2 * tx;
#pragma unroll
            for (int di = 0; di < DD; di++) {
                const float2* sp = (const float2*)(rp + di * HALO_WP);
                float s[10];
#pragma unroll
                for (int k = 0; k < 5; k++) {
                    float2 v = sp[k];
                    s[2 * k]     = v.x;
                    s[2 * k + 1] = v.y;
                }
#pragma unroll
                for (int dj = 0; dj < DD; dj++) {
                    acc0[di * DD + dj] = fmaf(f0a, s[dj],     acc0[di * DD + dj]);
                    acc1[di * DD + dj] = fmaf(f0b, s[dj + 1], acc1[di * DD + dj]);
                }
            }
        }
        __syncthreads();
        if (ci + 2 < NCHUNK) issue((ci + 2) * CC, ci & 1);
#pragma unroll
        for (int cc = 0; cc < CC; cc++) f0cur[cc] = f0nxt[cc];
    }

    // ---- coalesced output via smem staging (2 tile-rows per pass) ----
#pragma unroll 1
    for (int g = 0; g < TILE_H / 2; g++) {
        __syncthreads();
        if ((ty >> 1) == g) {
            float* st = &smem[(ty & 1) * (TILE_W * NSH) + (2 * tx) * NSH];
#pragma unroll
            for (int s = 0; s < NSH; s++) {
                st[s]       = acc0[s];
                st[NSH + s] = acc1[s];
            }
        }
        __syncthreads();
#pragma unroll 1
        for (int rr = 0; rr < 2; rr++) {
            float2* dst = (float2*)(out +
                ((size_t)(b * HH + h0 + 2 * g + rr) * WW + w0) * NSH);
            const float2* src = (const float2*)&smem[rr * (TILE_W * NSH)];
            for (int i = tid; i < TILE_W * NSH / 2; i += NTHR) dst[i] = src[i];
        }
    }
}

extern "C" void kernel_launch(void* const* d_in, const int* in_sizes, int n_in,
                              void* d_out, int out_size)
{
    const float* FM0 = (const float*)d_in[0];
    const float* FM1 = (const float*)d_in[1];
    float* out = (float*)d_out;

    dim3 grid(WW / TILE_W, HH / TILE_H, BATCH);  // (3, 6, 8) = 144 blocks: one wave
    dim3 block(BX, BY);                           // 256 threads
    corr_kernel<<<grid, block>>>(FM0, FM1, out);
}

// round 3
// speedup vs baseline: 2.3628x; 1.2172x over previous
#include <cuda_runtime.h>
#include <cuda_bf16.h>
#include <cstdint>

#define BATCH 8
#define CH    256
#define HH    96
#define WW    96
#define HW    (HH*WW)
#define DMAX  4
#define DD    9
#define NSH   81
#define TILE_W 32
#define TILE_H 16
#define BX 16
#define BY 16
#define NTHR 256
#define CC 4
#define NCHUNK (CH/CC)
#define HALO_H (TILE_H + 2*DMAX)   // 24
#define HALO_W (TILE_W + 2*DMAX)   // 40
#define HALO_WP 42
#define CHUNK_WORDS (CC*HALO_H*HALO_WP)   // 4032
#define LOG_WORDS   (CC*HALO_H*HALO_W)    // 3840
#define NLOAD (LOG_WORDS/NTHR)            // 15

typedef unsigned long long u64;

__device__ __forceinline__ void cp_async4(uint32_t dst, const void* src, int sz) {
    asm volatile("cp.async.ca.shared.global [%0], [%1], 4, %2;\n"
                 :: "r"(dst), "l"(src), "r"(sz));
}
__device__ __forceinline__ void ffma2(u64& acc, u64 a, u64 b) {
    asm("fma.rn.f32x2 %0, %1, %2, %3;" : "=l"(acc) : "l"(a), "l"(b), "l"(acc));
}
__device__ __forceinline__ u64 pack2(float x, float y) {
    u64 d; asm("mov.b64 %0, {%1, %2};" : "=l"(d) : "f"(x), "f"(y)); return d;
}
__device__ __forceinline__ void unpack2(u64 d, float& x, float& y) {
    asm("mov.b64 {%0, %1}, %2;" : "=f"(x), "=f"(y) : "l"(d));
}
__device__ __forceinline__ float lo32(u64 d) {
    float x, y; unpack2(d, x, y); return x;
}
__device__ __forceinline__ float hi32(u64 d) {
    float x, y; unpack2(d, x, y); return y;
}

__global__ __launch_bounds__(256, 1)
void corr_kernel(const float* __restrict__ FM0,
                 const float* __restrict__ FM1,
                 float* __restrict__ out)
{
    __shared__ float smem[2 * CHUNK_WORDS];

    const int tx  = threadIdx.x;
    const int ty  = threadIdx.y;
    const int tid = ty * BX + tx;
    const int w0  = blockIdx.x * TILE_W;
    const int h0  = blockIdx.y * TILE_H;
    const int b   = blockIdx.z;
    const int w   = w0 + 2 * tx;
    const int h   = h0 + ty;

    // gather tables for the FM1 halo chunk
    int dstw[NLOAD];
    int srcw[NLOAD];
#pragma unroll
    for (int j = 0; j < NLOAD; j++) {
        int idx = tid + NTHR * j;
        int cc  = idx / (HALO_H * HALO_W);
        int rem = idx - cc * (HALO_H * HALO_W);
        int r   = rem / HALO_W;
        int col = rem - r * HALO_W;
        dstw[j] = (cc * HALO_H + r) * HALO_WP + col;
        int gh = h0 - DMAX + r;
        int gw = w0 - DMAX + col;
        srcw[j] = ((unsigned)gh < HH && (unsigned)gw < WW)
                    ? cc * HW + gh * WW + gw : -1;
    }

    const float* f1b = FM1 + (size_t)b * CH * HW;
    const uint32_t sbase = (uint32_t)__cvta_generic_to_shared(smem);

    auto issue = [&](int c0, int buf) {
#pragma unroll
        for (int j = 0; j < NLOAD; j++) {
            uint32_t d = sbase + (uint32_t)(buf * CHUNK_WORDS + dstw[j]) * 4u;
            int sw = srcw[j];
            const float* s = f1b + (size_t)c0 * HW + (sw < 0 ? 0 : sw);
            cp_async4(d, s, sw < 0 ? 0 : 4);
        }
        asm volatile("cp.async.commit_group;\n" ::: "memory");
    };

    // Accumulators: per pixel, 9 rows x (4 packed f32x2 pairs + 1 scalar).
    // acc0 (pixel w): pairs cover dj=(0,1)(2,3)(4,5)(6,7), scalar dj=8.
    // acc1 (pixel w+1): scalar dj=0, pairs cover dj=(1,2)(3,4)(5,6)(7,8).
    u64   A0[DD * 4], A1[DD * 4];
    float S0[DD], S1[DD];
#pragma unroll
    for (int i = 0; i < DD * 4; i++) { A0[i] = 0ull; A1[i] = 0ull; }
#pragma unroll
    for (int i = 0; i < DD; i++) { S0[i] = 0.f; S1[i] = 0.f; }

    const float* f0p = FM0 + ((size_t)b * CH) * HW + (size_t)h * WW + w;

    issue(0, 0);
    issue(CC, 1);
    float2 f0cur[CC], f0nxt[CC];
#pragma unroll
    for (int cc = 0; cc < CC; cc++)
        f0cur[cc] = __ldg((const float2*)(f0p + (size_t)cc * HW));

#pragma unroll 1
    for (int ci = 0; ci < NCHUNK; ci++) {
        if (ci < NCHUNK - 1)
            asm volatile("cp.async.wait_group 1;\n" ::: "memory");
        else
            asm volatile("cp.async.wait_group 0;\n" ::: "memory");
        __syncthreads();

        if (ci + 1 < NCHUNK) {
            const int cn = (ci + 1) * CC;
#pragma unroll
            for (int cc = 0; cc < CC; cc++)
                f0nxt[cc] = __ldg((const float2*)(f0p + (size_t)(cn + cc) * HW));
        }

        const float* sb = &smem[(ci & 1) * CHUNK_WORDS];
#pragma unroll
        for (int cc = 0; cc < CC; cc++) {
            const float f0a = f0cur[cc].x;
            const float f0b = f0cur[cc].y;
            const u64 fa2 = pack2(f0a, f0a);
            const u64 fb2 = pack2(f0b, f0b);
            const float* rp = sb + (cc * HALO_H + ty) * HALO_WP + 2 * tx;
#pragma unroll
            for (int di = 0; di < DD; di++) {
                const u64* sp = (const u64*)(rp + di * HALO_WP);
                u64 v0 = sp[0], v1 = sp[1], v2 = sp[2], v3 = sp[3], v4 = sp[4];
                // pixel w: dj pairs (0,1)(2,3)(4,5)(6,7) <- v0..v3, scalar dj=8 <- lo(v4)
                ffma2(A0[di * 4 + 0], fa2, v0);
                ffma2(A0[di * 4 + 1], fa2, v1);
                ffma2(A0[di * 4 + 2], fa2, v2);
                ffma2(A0[di * 4 + 3], fa2, v3);
                S0[di] = fmaf(f0a, lo32(v4), S0[di]);
                // pixel w+1: dj pairs (1,2)(3,4)(5,6)(7,8) <- v1..v4, scalar dj=0 <- hi(v0)
                ffma2(A1[di * 4 + 0], fb2, v1);
                ffma2(A1[di * 4 + 1], fb2, v2);
                ffma2(A1[di * 4 + 2], fb2, v3);
                ffma2(A1[di * 4 + 3], fb2, v4);
                S1[di] = fmaf(f0b, hi32(v0), S1[di]);
            }
        }
        __syncthreads();
        if (ci + 2 < NCHUNK) issue((ci + 2) * CC, ci & 1);
#pragma unroll
        for (int cc = 0; cc < CC; cc++) f0cur[cc] = f0nxt[cc];
    }

    // ---- unpack accumulators into scalar layout ----
    float acc0[NSH], acc1[NSH];
#pragma unroll
    for (int di = 0; di < DD; di++) {
#pragma unroll
        for (int p = 0; p < 4; p++) {
            float x, y;
            unpack2(A0[di * 4 + p], x, y);
            acc0[di * DD + 2 * p]     = x;
            acc0[di * DD + 2 * p + 1] = y;
            unpack2(A1[di * 4 + p], x, y);
            acc1[di * DD + 2 * p + 1] = x;
            acc1[di * DD + 2 * p + 2] = y;
        }
        acc0[di * DD + 8] = S0[di];
        acc1[di * DD + 0] = S1[di];
    }

    // ---- coalesced output via smem staging ----
#pragma unroll 1
    for (int g = 0; g < TILE_H / 2; g++) {
        __syncthreads();
        if ((ty >> 1) == g) {
            float* st = &smem[(ty & 1) * (TILE_W * NSH) + (2 * tx) * NSH];
#pragma unroll
            for (int s = 0; s < NSH; s++) {
                st[s]       = acc0[s];
                st[NSH + s] = acc1[s];
            }
        }
        __syncthreads();
#pragma unroll 1
        for (int rr = 0; rr < 2; rr++) {
            float2* dst = (float2*)(out +
                ((size_t)(b * HH + h0 + 2 * g + rr) * WW + w0) * NSH);
            const float2* src = (const float2*)&smem[rr * (TILE_W * NSH)];
            for (int i = tid; i < TILE_W * NSH / 2; i += NTHR) dst[i] = src[i];
        }
    }
}

extern "C" void kernel_launch(void* const* d_in, const int* in_sizes, int n_in,
                              void* d_out, int out_size)
{
    const float* FM0 = (const float*)d_in[0];
    const float* FM1 = (const float*)d_in[1];
    float* out = (float*)d_out;

    dim3 grid(WW / TILE_W, HH / TILE_H, BATCH);  // 144 blocks, one wave
    dim3 block(BX, BY);
    corr_kernel<<<grid, block>>>(FM0, FM1, out);
}

// round 4
// speedup vs baseline: 2.9267x; 1.2387x over previous
#include <cuda_runtime.h>
#include <cstdint>

#define BATCH 8
#define CH    256
#define HH    96
#define WW    96
#define HW    (HH*WW)
#define DMAX  4
#define DD    9
#define NSH   81
#define TILE_W 32
#define TILE_H 16
#define BX 16
#define BYY 32
#define NTHR 512
#define CC 4
#define NCHUNK (CH/CC)                 // 64
#define HALO_H 24
#define HALO_W 40
#define F1_WORDS (CC*HALO_H*HALO_W)    // 3840
#define F0_WORDS (CC*TILE_H*TILE_W)    // 2048
#define BUF_WORDS (F1_WORDS+F0_WORDS)  // 5888 -> 2 bufs = 47104 B smem
#define NF4 (CC*HALO_H*(HALO_W/4))     // 960 float4 loads (FM1) per chunk

typedef unsigned long long u64;

__device__ __forceinline__ void cp16(uint32_t dst, const void* src, int sz) {
    asm volatile("cp.async.cg.shared.global [%0], [%1], 16, %2;\n"
                 :: "r"(dst), "l"(src), "r"(sz));
}
__device__ __forceinline__ void ffma2(u64& acc, u64 a, u64 b) {
    asm("fma.rn.f32x2 %0, %1, %2, %3;" : "=l"(acc) : "l"(a), "l"(b), "l"(acc));
}
__device__ __forceinline__ u64 pack2(float x, float y) {
    u64 d; asm("mov.b64 %0, {%1, %2};" : "=l"(d) : "f"(x), "f"(y)); return d;
}
__device__ __forceinline__ void unpack2(u64 d, float& x, float& y) {
    asm("mov.b64 {%0, %1}, %2;" : "=f"(x), "=f"(y) : "l"(d));
}
__device__ __forceinline__ float lo32(u64 d) { float x,y; unpack2(d,x,y); return x; }
__device__ __forceinline__ float hi32(u64 d) { float x,y; unpack2(d,x,y); return y; }

__global__ __launch_bounds__(512, 1)
void corr_kernel(const float* __restrict__ FM0,
                 const float* __restrict__ FM1,
                 float* __restrict__ out)
{
    __shared__ alignas(16) float smem[2 * BUF_WORDS];

    const int tx  = threadIdx.x;          // 0..15
    const int tyF = threadIdx.y;          // 0..31
    const int tid = tyF * BX + tx;
    const int grp = tyF >> 4;             // 0: di 0-4 (warps 0-7), 1: di 5-8
    const int ty  = tyF & 15;             // pixel row in tile
    const int w0  = blockIdx.x * TILE_W;
    const int h0  = blockIdx.y * TILE_H;
    const int b   = blockIdx.z;

    // ---- FM1 halo gather table (float4 granularity; edges fully-in or fully-out) ----
    int dstw[2], srcw[2];
#pragma unroll
    for (int j = 0; j < 2; j++) {
        int idx = tid + NTHR * j;         // j=1 valid iff idx < 960 (tid < 448)
        int cc  = idx / (HALO_H * (HALO_W/4));
        int rem = idx - cc * (HALO_H * (HALO_W/4));
        int r   = rem / (HALO_W/4);
        int c4  = rem - r * (HALO_W/4);
        dstw[j] = (cc * HALO_H + r) * HALO_W + 4 * c4;
        int gh = h0 - DMAX + r;
        int gw = w0 - DMAX + 4 * c4;      // 4-aligned; fully in or fully out of [0,96)
        srcw[j] = ((unsigned)gh < HH && (unsigned)gw < WW)
                    ? cc * HW + gh * WW + gw : -1;
    }
    const bool j1v = (tid < NF4 - NTHR);  // tid < 448

    // ---- FM0 stage mapping: one float4 per thread per chunk ----
    const int f0cc  = tid >> 7;
    const int f0rem = tid & 127;
    const int f0row = f0rem >> 3;
    const int f0c4  = f0rem & 7;
    const int f0dst = F1_WORDS + (f0cc * TILE_H + f0row) * TILE_W + 4 * f0c4;
    const float* f0base = FM0 + (size_t)b * CH * HW;
    const size_t f0off  = (size_t)f0cc * HW + (size_t)(h0 + f0row) * WW + w0 + 4 * f0c4;

    const float* f1b = FM1 + (size_t)b * CH * HW;
    const uint32_t sbase = (uint32_t)__cvta_generic_to_shared(smem);

    auto issue = [&](int c0, int buf) {
        uint32_t base = sbase + (uint32_t)(buf * BUF_WORDS) * 4u;
#pragma unroll
        for (int j = 0; j < 2; j++) {
            if (j == 0 || j1v) {
                int sw = srcw[j];
                const float* s = f1b + (size_t)c0 * HW + (sw < 0 ? 0 : sw);
                cp16(base + (uint32_t)dstw[j] * 4u, s, sw < 0 ? 0 : 16);
            }
        }
        cp16(base + (uint32_t)f0dst * 4u, f0base + f0off + (size_t)c0 * HW, 16);
        asm volatile("cp.async.commit_group;\n" ::: "memory");
    };

    // Accumulators for up to 5 shift-rows of a 2-pixel pair.
    // Even pixel: pairs dj(0,1)(2,3)(4,5)(6,7) + scalar dj8.
    // Odd pixel:  scalar dj0 + pairs dj(1,2)(3,4)(5,6)(7,8).
    u64   A0[20], A1[20];
    float S0[5],  S1[5];
#pragma unroll
    for (int i = 0; i < 20; i++) { A0[i] = 0ull; A1[i] = 0ull; }
#pragma unroll
    for (int i = 0; i < 5; i++)  { S0[i] = 0.f;  S1[i] = 0.f; }

    issue(0, 0);
    issue(CC, 1);

#pragma unroll 1
    for (int ci = 0; ci < NCHUNK; ci++) {
        if (ci < NCHUNK - 1)
            asm volatile("cp.async.wait_group 1;\n" ::: "memory");
        else
            asm volatile("cp.async.wait_group 0;\n" ::: "memory");
        __syncthreads();

        const float* sb = &smem[(ci & 1) * BUF_WORDS];

        auto row = [&](int di, int ridx, const float* rp, u64 fa2, u64 fb2,
                       float f0a, float f0b) {
            const u64* sp = (const u64*)(rp + di * HALO_W);
            u64 v0 = sp[0], v1 = sp[1], v2 = sp[2], v3 = sp[3], v4 = sp[4];
            ffma2(A0[ridx * 4 + 0], fa2, v0);
            ffma2(A0[ridx * 4 + 1], fa2, v1);
            ffma2(A0[ridx * 4 + 2], fa2, v2);
            ffma2(A0[ridx * 4 + 3], fa2, v3);
            S0[ridx] = fmaf(f0a, lo32(v4), S0[ridx]);
            ffma2(A1[ridx * 4 + 0], fb2, v1);
            ffma2(A1[ridx * 4 + 1], fb2, v2);
            ffma2(A1[ridx * 4 + 2], fb2, v3);
            ffma2(A1[ridx * 4 + 3], fb2, v4);
            S1[ridx] = fmaf(f0b, hi32(v0), S1[ridx]);
        };

        if (grp == 0) {
#pragma unroll
            for (int cc = 0; cc < CC; cc++) {
                float2 f0 = *(const float2*)(sb + F1_WORDS +
                                             (cc * TILE_H + ty) * TILE_W + 2 * tx);
                const u64 fa2 = pack2(f0.x, f0.x);
                const u64 fb2 = pack2(f0.y, f0.y);
                const float* rp = sb + (cc * HALO_H + ty) * HALO_W + 2 * tx;
#pragma unroll
                for (int r = 0; r < 5; r++) row(r, r, rp, fa2, fb2, f0.x, f0.y);
            }
        } else {
#pragma unroll
            for (int cc = 0; cc < CC; cc++) {
                float2 f0 = *(const float2*)(sb + F1_WORDS +
                                             (cc * TILE_H + ty) * TILE_W + 2 * tx);
                const u64 fa2 = pack2(f0.x, f0.x);
                const u64 fb2 = pack2(f0.y, f0.y);
                const float* rp = sb + (cc * HALO_H + ty) * HALO_W + 2 * tx;
#pragma unroll
                for (int r = 0; r < 4; r++) row(5 + r, r, rp, fa2, fb2, f0.x, f0.y);
            }
        }

        __syncthreads();
        if (ci + 2 < NCHUNK) issue((ci + 2) * CC, ci & 1);
    }

    // ---- coalesced output via smem staging: 4 tile-rows per pass ----
    const int di0 = grp ? 5 : 0;
    const int nr  = grp ? 4 : 5;
#pragma unroll 1
    for (int g = 0; g < TILE_H / 4; g++) {
        __syncthreads();
        if ((ty >> 2) == g) {
            float* st = &smem[(size_t)((ty & 3) * TILE_W + 2 * tx) * NSH];
#pragma unroll
            for (int r = 0; r < 5; r++) {
                if (r >= nr) break;
                const int base = (di0 + r) * DD;
#pragma unroll
                for (int p = 0; p < 4; p++) {
                    float x, y;
                    unpack2(A0[r * 4 + p], x, y);
                    st[base + 2 * p]           = x;
                    st[base + 2 * p + 1]       = y;
                    unpack2(A1[r * 4 + p], x, y);
                    st[NSH + base + 2 * p + 1] = x;
                    st[NSH + base + 2 * p + 2] = y;
                }
                st[base + 8]       = S0[r];
                st[NSH + base + 0] = S1[r];
            }
        }
        __syncthreads();
#pragma unroll 1
        for (int rr = 0; rr < 4; rr++) {
            float2* dst = (float2*)(out +
                ((size_t)(b * HH + h0 + 4 * g + rr) * WW + w0) * NSH);
            const float2* src = (const float2*)&smem[rr * (TILE_W * NSH)];
            for (int i = tid; i < TILE_W * NSH / 2; i += NTHR) dst[i] = src[i];
        }
    }
}

extern "C" void kernel_launch(void* const* d_in, const int* in_sizes, int n_in,
                              void* d_out, int out_size)
{
    const float* FM0 = (const float*)d_in[0];
    const float* FM1 = (const float*)d_in[1];
    float* out = (float*)d_out;

    dim3 grid(WW / TILE_W, HH / TILE_H, BATCH);  // 144 blocks, one wave
    dim3 block(BX, BYY);                          // 512 threads
    corr_kernel<<<grid, block>>>(FM0, FM1, out);
}

// round 6
// speedup vs baseline: 3.8416x; 1.3126x over previous
#include <cuda_runtime.h>
#include <cstdint>

#define BATCH 8
#define CH    256
#define HH    96
#define WW    96
#define HW    (HH*WW)
#define DMAX  4
#define DD    9
#define NSH   81
#define TILE_W 32
#define TILE_H 16
#define NTHR  384                       // (8,16,3)
#define CC    4
#define NCHUNK (CH/CC)                  // 64
#define HALO_H 24
#define HALO_W 40
#define HALO_WP 42                      // conflict-free stride for LDS.64 pattern
#define F1_WORDS (CC*HALO_H*HALO_WP)    // 4032
#define F0_WORDS (CC*TILE_H*TILE_W)     // 2048
#define BUF_WORDS (F1_WORDS+F0_WORDS)   // 6080 -> 2 bufs = 48640 B
#define NF8 (CC*HALO_H*(HALO_W/2))      // 1920 8B copies -> 5/thread

typedef unsigned long long u64;

__device__ __forceinline__ void cp8(uint32_t dst, const void* src, int sz) {
    asm volatile("cp.async.ca.shared.global [%0], [%1], 8, %2;\n"
                 :: "r"(dst), "l"(src), "r"(sz));
}
__device__ __forceinline__ void cp16(uint32_t dst, const void* src) {
    asm volatile("cp.async.cg.shared.global [%0], [%1], 16;\n"
                 :: "r"(dst), "l"(src));
}
__device__ __forceinline__ void ffma2(u64& acc, u64 a, u64 b) {
    asm("fma.rn.f32x2 %0, %1, %2, %3;" : "=l"(acc) : "l"(a), "l"(b), "l"(acc));
}
__device__ __forceinline__ u64 pack2(float x, float y) {
    u64 d; asm("mov.b64 %0, {%1, %2};" : "=l"(d) : "f"(x), "f"(y)); return d;
}
__device__ __forceinline__ void unpack2(u64 d, float& x, float& y) {
    asm("mov.b64 {%0, %1}, %2;" : "=f"(x), "=f"(y) : "l"(d));
}
__device__ __forceinline__ float lo32(u64 d) { float x,y; unpack2(d,x,y); return x; }
__device__ __forceinline__ float hi32(u64 d) { float x,y; unpack2(d,x,y); return y; }

__global__ __launch_bounds__(NTHR, 1)
void corr_kernel(const float* __restrict__ FM0,
                 const float* __restrict__ FM1,
                 float* __restrict__ out)
{
    __shared__ alignas(16) float smem[2 * BUF_WORDS];

    const int tx  = threadIdx.x;          // 0..7  : 4 pixels each
    const int ty  = threadIdx.y;          // 0..15 : pixel row
    const int tz  = threadIdx.z;          // 0..2  : shift-row group (di = 3tz..3tz+2)
    const int tid = (tz * TILE_H + ty) * 8 + tx;
    const int w0  = blockIdx.x * TILE_W;
    const int h0  = blockIdx.y * TILE_H;
    const int b   = blockIdx.z;

    // ---- FM1 halo gather table: 5 x 8B cp.async per thread per chunk ----
    int dstw[5], srcw[5];
#pragma unroll
    for (int j = 0; j < 5; j++) {
        int idx = tid + NTHR * j;             // < 1920
        int cc  = idx / (HALO_H * (HALO_W/2));
        int rem = idx - cc * (HALO_H * (HALO_W/2));
        int r   = rem / (HALO_W/2);
        int c8  = rem - r * (HALO_W/2);
        dstw[j] = (cc * HALO_H + r) * HALO_WP + 2 * c8;
        int gh = h0 - DMAX + r;
        int gw = w0 - DMAX + 2 * c8;          // 2-aligned: fully in or out of [0,96)
        srcw[j] = ((unsigned)gh < HH && (unsigned)gw < WW)
                    ? cc * HW + gh * WW + gw : -1;
    }

    // ---- FM0 stage mapping: float4 copies (512 total; threads 0..127 do two) ----
    const float* f0base = FM0 + (size_t)b * CH * HW;
    int f0dst[2]; size_t f0off[2];
#pragma unroll
    for (int j = 0; j < 2; j++) {
        int idx = tid + NTHR * j;             // valid if < 512
        int cc  = idx >> 7;
        int rem = idx & 127;
        int row = rem >> 3;
        int c4  = rem & 7;
        f0dst[j] = F1_WORDS + (cc * TILE_H + row) * TILE_W + 4 * c4;
        f0off[j] = (size_t)cc * HW + (size_t)(h0 + row) * WW + w0 + 4 * c4;
    }
    const bool f0v1 = (tid < 512 - NTHR);     // tid < 128

    const float* f1b = FM1 + (size_t)b * CH * HW;
    const uint32_t sbase = (uint32_t)__cvta_generic_to_shared(smem);

    auto issue = [&](int c0, int buf) {
        uint32_t base = sbase + (uint32_t)(buf * BUF_WORDS) * 4u;
#pragma unroll
        for (int j = 0; j < 5; j++) {
            int sw = srcw[j];
            const float* s = f1b + (size_t)c0 * HW + (sw < 0 ? 0 : sw);
            cp8(base + (uint32_t)dstw[j] * 4u, s, sw < 0 ? 0 : 8);
        }
        cp16(base + (uint32_t)f0dst[0] * 4u, f0base + f0off[0] + (size_t)c0 * HW);
        if (f0v1)
            cp16(base + (uint32_t)f0dst[1] * 4u, f0base + f0off[1] + (size_t)c0 * HW);
        asm volatile("cp.async.commit_group;\n" ::: "memory");
    };

    // Accumulators: P[r][px][pair], S[r][px]  (3 rows x 4 px x (4 f32x2 + 1 scalar))
    u64   P[3][4][4];
    float S[3][4];
#pragma unroll
    for (int r = 0; r < 3; r++) {
#pragma unroll
        for (int i = 0; i < 4; i++) {
            S[r][i] = 0.f;
#pragma unroll
            for (int p = 0; p < 4; p++) P[r][i][p] = 0ull;
        }
    }

    issue(0, 0);
    issue(CC, 1);

#pragma unroll 1
    for (int ci = 0; ci < NCHUNK; ci++) {
        if (ci < NCHUNK - 1)
            asm volatile("cp.async.wait_group 1;\n" ::: "memory");
        else
            asm volatile("cp.async.wait_group 0;\n" ::: "memory");
        __syncthreads();

        const float* sb = &smem[(ci & 1) * BUF_WORDS];
#pragma unroll
        for (int cc = 0; cc < CC; cc++) {
            float4 f0 = *(const float4*)(sb + F1_WORDS +
                                         (cc * TILE_H + ty) * TILE_W + 4 * tx);
            const u64 fa0 = pack2(f0.x, f0.x);
            const u64 fa1 = pack2(f0.y, f0.y);
            const u64 fa2 = pack2(f0.z, f0.z);
            const u64 fa3 = pack2(f0.w, f0.w);
            const float* rp = sb + (cc * HALO_H + ty + 3 * tz) * HALO_WP + 4 * tx;
#pragma unroll
            for (int r = 0; r < 3; r++) {
                const u64* sp = (const u64*)(rp + r * HALO_WP);
                u64 v0 = sp[0], v1 = sp[1], v2 = sp[2],
                    v3 = sp[3], v4 = sp[4], v5 = sp[5];
                // px0 (cols 4tx+0..8): pairs v0..v3, scalar dj8 = v4.lo
                ffma2(P[r][0][0], fa0, v0); ffma2(P[r][0][1], fa0, v1);
                ffma2(P[r][0][2], fa0, v2); ffma2(P[r][0][3], fa0, v3);
                S[r][0] = fmaf(f0.x, lo32(v4), S[r][0]);
                // px1 (cols 4tx+1..9): scalar dj0 = v0.hi, pairs v1..v4
                ffma2(P[r][1][0], fa1, v1); ffma2(P[r][1][1], fa1, v2);
                ffma2(P[r][1][2], fa1, v3); ffma2(P[r][1][3], fa1, v4);
                S[r][1] = fmaf(f0.y, hi32(v0), S[r][1]);
                // px2 (cols 4tx+2..10): pairs v1..v4, scalar dj8 = v5.lo
                ffma2(P[r][2][0], fa2, v1); ffma2(P[r][2][1], fa2, v2);
                ffma2(P[r][2][2], fa2, v3); ffma2(P[r][2][3], fa2, v4);
                S[r][2] = fmaf(f0.z, lo32(v5), S[r][2]);
                // px3 (cols 4tx+3..11): scalar dj0 = v1.hi, pairs v2..v5
                ffma2(P[r][3][0], fa3, v2); ffma2(P[r][3][1], fa3, v3);
                ffma2(P[r][3][2], fa3, v4); ffma2(P[r][3][3], fa3, v5);
                S[r][3] = fmaf(f0.w, hi32(v1), S[r][3]);
            }
        }

        __syncthreads();
        if (ci + 2 < NCHUNK) issue((ci + 2) * CC, ci & 1);
    }

    // ---- coalesced output via smem staging: 4 tile-rows per pass, PER-ROW copies ----
#pragma unroll 1
    for (int g = 0; g < TILE_H / 4; g++) {
        __syncthreads();
        if ((ty >> 2) == g) {
            float* st = &smem[(size_t)((ty & 3) * TILE_W + 4 * tx) * NSH];
#pragma unroll
            for (int r = 0; r < 3; r++) {
                const int base = (3 * tz + r) * DD;
                float x, y;
#pragma unroll
                for (int p = 0; p < 4; p++) {
                    unpack2(P[r][0][p], x, y);
                    st[0 * NSH + base + 2 * p]     = x;
                    st[0 * NSH + base + 2 * p + 1] = y;
                    unpack2(P[r][1][p], x, y);
                    st[1 * NSH + base + 2 * p + 1] = x;
                    st[1 * NSH + base + 2 * p + 2] = y;
                    unpack2(P[r][2][p], x, y);
                    st[2 * NSH + base + 2 * p]     = x;
                    st[2 * NSH + base + 2 * p + 1] = y;
                    unpack2(P[r][3][p], x, y);
                    st[3 * NSH + base + 2 * p + 1] = x;
                    st[3 * NSH + base + 2 * p + 2] = y;
                }
                st[0 * NSH + base + 8] = S[r][0];
                st[1 * NSH + base + 0] = S[r][1];
                st[2 * NSH + base + 8] = S[r][2];
                st[3 * NSH + base + 0] = S[r][3];
            }
        }
        __syncthreads();
#pragma unroll 1
        for (int rr = 0; rr < 4; rr++) {
            // out rows stride WW*NSH; tile rows are NOT contiguous -> copy per row.
            float4* dst = (float4*)(out +
                ((size_t)(b * HH + h0 + 4 * g + rr) * WW + w0) * NSH);
            const float4* src = (const float4*)&smem[rr * (TILE_W * NSH)];
            for (int i = tid; i < TILE_W * NSH / 4; i += NTHR) dst[i] = src[i];
        }
    }
}

extern "C" void kernel_launch(void* const* d_in, const int* in_sizes, int n_in,
                              void* d_out, int out_size)
{
    const float* FM0 = (const float*)d_in[0];
    const float* FM1 = (const float*)d_in[1];
    float* out = (float*)d_out;

    dim3 grid(WW / TILE_W, HH / TILE_H, BATCH);  // 144 blocks, one wave
    dim3 block(8, TILE_H, 3);                     // 384 threads
    corr_kernel<<<grid, block>>>(FM0, FM1, out);
}